// round 1
// baseline (speedup 1.0000x reference)
#include <cuda_runtime.h>

#define B_SZ 256
#define T_SZ 2000
#define F_SZ 128

// Scratch (device globals — no allocation allowed)
__device__ float g_curT[T_SZ * B_SZ];   // cur transposed: [T, B]
__device__ float g_spkT[T_SZ * B_SZ];   // spikes transposed: [T, B]

// BETA = sigmoid(2.0), VTH = 1.0
#define BETA_F 0.8807970779778823f

// ---------------------------------------------------------------------------
// Kernel 1: cur[t*B + b] = dot(x[b,t,:], W[:,0]) + bias
// One warp per (b,t) row. 512B coalesced float4 loads per warp.
// ---------------------------------------------------------------------------
__global__ void __launch_bounds__(256) lif_gemv_kernel(
    const float* __restrict__ x, const float* __restrict__ W,
    const float* __restrict__ bias)
{
    int warp = (blockIdx.x * blockDim.x + threadIdx.x) >> 5;
    int lane = threadIdx.x & 31;
    if (warp >= B_SZ * T_SZ) return;

    const float4 xv = reinterpret_cast<const float4*>(x + (size_t)warp * F_SZ)[lane];
    const float4 wv = reinterpret_cast<const float4*>(W)[lane];

    float s = xv.x * wv.x + xv.y * wv.y + xv.z * wv.z + xv.w * wv.w;
    s += __shfl_xor_sync(0xFFFFFFFFu, s, 16);
    s += __shfl_xor_sync(0xFFFFFFFFu, s, 8);
    s += __shfl_xor_sync(0xFFFFFFFFu, s, 4);
    s += __shfl_xor_sync(0xFFFFFFFFu, s, 2);
    s += __shfl_xor_sync(0xFFFFFFFFu, s, 1);

    if (lane == 0) {
        int b = warp / T_SZ;
        int t = warp - b * T_SZ;
        g_curT[t * B_SZ + b] = s + bias[0];
    }
}

// ---------------------------------------------------------------------------
// Kernel 2: sequential LIF scan over T, one thread per batch row.
// 8 blocks x 32 threads -> spread across 8 SMs, coalesced 128B warp loads.
// ---------------------------------------------------------------------------
__global__ void __launch_bounds__(32) lif_scan_kernel(float* __restrict__ out,
                                                      int out_size)
{
    int b = blockIdx.x * 32 + threadIdx.x;
    float v = 0.0f;

    #pragma unroll 8
    for (int t = 0; t < T_SZ; ++t) {
        float c = g_curT[t * B_SZ + b];
        v = fmaf(BETA_F, v, c);              // leaky integrate
        float s = (v >= 1.0f) ? 1.0f : 0.0f; // threshold (VTH = 1)
        v -= s;                              // subtraction reset
        g_spkT[t * B_SZ + b] = s;
    }

    // final membrane potential vT, appended after spikes in d_out
    if (out_size > B_SZ * T_SZ)
        out[B_SZ * T_SZ + b] = v;
}

// ---------------------------------------------------------------------------
// Kernel 3: transpose spikes [T,B] -> d_out [B,T] via 32x32 smem tiles.
// grid = (B/32, ceil(T/32)), block = (32, 8)
// ---------------------------------------------------------------------------
__global__ void __launch_bounds__(256) lif_transpose_kernel(float* __restrict__ out)
{
    __shared__ float tile[32][33];
    int b0 = blockIdx.x * 32;
    int t0 = blockIdx.y * 32;
    int tx = threadIdx.x;
    int ty = threadIdx.y;

    #pragma unroll
    for (int i = 0; i < 32; i += 8) {
        int t = t0 + ty + i;
        if (t < T_SZ)
            tile[ty + i][tx] = g_spkT[t * B_SZ + (b0 + tx)];
    }
    __syncthreads();
    #pragma unroll
    for (int i = 0; i < 32; i += 8) {
        int t = t0 + tx;
        int b = b0 + ty + i;
        if (t < T_SZ)
            out[(size_t)b * T_SZ + t] = tile[tx][ty + i];
    }
}

// ---------------------------------------------------------------------------
extern "C" void kernel_launch(void* const* d_in, const int* in_sizes, int n_in,
                              void* d_out, int out_size)
{
    const float* x    = (const float*)d_in[0];  // [256, 2000, 128] fp32
    const float* W    = (const float*)d_in[1];  // [128, 1] fp32
    const float* bias = (const float*)d_in[2];  // [1] fp32
    float* out = (float*)d_out;                 // spikes [256*2000] then vT [256]

    // Kernel 1: 512000 rows, 8 warps (rows) per 256-thread block
    {
        int total_warps = B_SZ * T_SZ;
        int blocks = (total_warps + 7) / 8;
        lif_gemv_kernel<<<blocks, 256>>>(x, W, bias);
    }

    // Kernel 2: 8 blocks x 32 threads = 256 scan lanes
    lif_scan_kernel<<<B_SZ / 32, 32>>>(out, out_size);

    // Kernel 3: transpose spikes into output layout
    {
        dim3 grid(B_SZ / 32, (T_SZ + 31) / 32);
        dim3 block(32, 8);
        lif_transpose_kernel<<<grid, block>>>(out);
    }
}

// round 2
// speedup vs baseline: 11.5864x; 11.5864x over previous
#include <cuda_runtime.h>

#define B_SZ 256
#define T_SZ 2000
#define F_SZ 128

#define CHUNK   80                 // timesteps per pipeline chunk
#define NCHUNK  (T_SZ / CHUNK)     // 25, exact
#define DOT_WARPS 8
#define T_PER_WARP (CHUNK / DOT_WARPS)  // 10
#define THREADS (32 * (DOT_WARPS + 1))  // 288: warp 0 = scan, warps 1..8 = dot

// BETA = sigmoid(2.0), VTH = 1.0
#define BETA_F 0.8807970779778823f

__global__ void __launch_bounds__(THREADS) lif_fused_kernel(
    const float* __restrict__ x, const float* __restrict__ W,
    const float* __restrict__ bias, float* __restrict__ out, int out_size)
{
    __shared__ float cur_s[2][CHUNK];

    const int b    = blockIdx.x;          // batch row
    const int wid  = threadIdx.x >> 5;
    const int lane = threadIdx.x & 31;

    // ---- dot-warp constants (held in registers) ----
    float4 wv;
    float  bias_v = 0.0f;
    if (wid > 0) {
        wv = reinterpret_cast<const float4*>(W)[lane];
        bias_v = bias[0];
    }

    // scan state (only warp 0 lane 0 uses it)
    float v = 0.0f;
    float4 spk4;
    float* out_row = out + (size_t)b * T_SZ;

    const float* xrow = x + (size_t)b * T_SZ * F_SZ;

    for (int c = 0; c < NCHUNK; ++c) {
        const int buf = c & 1;

        if (wid > 0) {
            // warps 1..8 compute dots for timesteps of chunk c
            const int t0 = c * CHUNK + (wid - 1) * T_PER_WARP;
            #pragma unroll
            for (int i = 0; i < T_PER_WARP; ++i) {
                const float4 xv = reinterpret_cast<const float4*>(
                    xrow + (size_t)(t0 + i) * F_SZ)[lane];
                float s = xv.x * wv.x + xv.y * wv.y + xv.z * wv.z + xv.w * wv.w;
                s += __shfl_xor_sync(0xFFFFFFFFu, s, 16);
                s += __shfl_xor_sync(0xFFFFFFFFu, s, 8);
                s += __shfl_xor_sync(0xFFFFFFFFu, s, 4);
                s += __shfl_xor_sync(0xFFFFFFFFu, s, 2);
                s += __shfl_xor_sync(0xFFFFFFFFu, s, 1);
                if (lane == 0)
                    cur_s[buf][(wid - 1) * T_PER_WARP + i] = s + bias_v;
            }
        }

        __syncthreads();   // chunk c dots visible

        // scan thread consumes chunk c while dot warps loop around and start
        // filling buffer buf^1 (chunk c+1). They can't reuse THIS buffer
        // (chunk c+2) until they pass the next barrier, which the scan thread
        // only reaches after finishing chunk c. 1-deep pipeline, safe.
        if (threadIdx.x == 0) {
            const int tbase = c * CHUNK;
            #pragma unroll 4
            for (int tl = 0; tl < CHUNK; ++tl) {
                float cu = cur_s[buf][tl];
                v = fmaf(BETA_F, v, cu);               // leaky integrate
                float s = (v >= 1.0f) ? 1.0f : 0.0f;   // threshold (VTH=1)
                v -= s;                                // subtraction reset
                ((float*)&spk4)[tl & 3] = s;
                if ((tl & 3) == 3)
                    reinterpret_cast<float4*>(out_row + tbase + (tl - 3))[0] = spk4;
            }
        }
    }

    // final membrane potential vT
    if (threadIdx.x == 0 && out_size > B_SZ * T_SZ)
        out[B_SZ * T_SZ + b] = v;
}

extern "C" void kernel_launch(void* const* d_in, const int* in_sizes, int n_in,
                              void* d_out, int out_size)
{
    const float* x    = (const float*)d_in[0];  // [256, 2000, 128] fp32
    const float* W    = (const float*)d_in[1];  // [128, 1] fp32
    const float* bias = (const float*)d_in[2];  // [1] fp32
    float* out = (float*)d_out;                 // spikes [256*2000] then vT [256]

    lif_fused_kernel<<<B_SZ, THREADS>>>(x, W, bias, out, out_size);
}

// round 3
// speedup vs baseline: 18.7532x; 1.6186x over previous
#include <cuda_runtime.h>

#define B_SZ 256
#define T_SZ 2000
#define F_SZ 128

#define CHUNK   80                 // timesteps per pipeline chunk
#define NCHUNK  (T_SZ / CHUNK)     // 25, exact
#define DOT_WARPS 8
#define T_PER_WARP (CHUNK / DOT_WARPS)  // 10
#define THREADS (32 * (DOT_WARPS + 1))  // 288: warp 0 = scan, warps 1..8 = dot

// BETA = sigmoid(2.0), VTH = 1.0
#define BETA_F 0.8807970779778823f

__global__ void __launch_bounds__(THREADS) lif_fused_kernel(
    const float* __restrict__ x, const float* __restrict__ W,
    const float* __restrict__ bias, float* __restrict__ out, int out_size)
{
    __shared__ float cur_s[2][CHUNK];

    const int b    = blockIdx.x;          // batch row
    const int wid  = threadIdx.x >> 5;
    const int lane = threadIdx.x & 31;

    // ---- dot-warp constants (held in registers) ----
    float4 wv;
    float  bias_v = 0.0f;
    if (wid > 0) {
        wv = reinterpret_cast<const float4*>(W)[lane];
        bias_v = bias[0];
    }

    // scan state (only warp 0 lane 0 uses it)
    float v = 0.0f;
    float4 spk4;
    float* out_row = out + (size_t)b * T_SZ;

    const float* xrow = x + (size_t)b * T_SZ * F_SZ;

    for (int c = 0; c < NCHUNK; ++c) {
        const int buf = c & 1;

        if (wid > 0) {
            const int t0 = c * CHUNK + (wid - 1) * T_PER_WARP;
            const float4* xp = reinterpret_cast<const float4*>(
                xrow + (size_t)t0 * F_SZ) + lane;

            // Phase 1: issue ALL loads for this warp's chunk slice (MLP=10,
            // 40KB in flight per block) before any dependent math.
            float4 xv[T_PER_WARP];
            #pragma unroll
            for (int i = 0; i < T_PER_WARP; ++i)
                xv[i] = xp[i * (F_SZ / 4)];

            // Phase 2: reduce each row; shuffle latencies pipeline across rows.
            #pragma unroll
            for (int i = 0; i < T_PER_WARP; ++i) {
                float s = xv[i].x * wv.x + xv[i].y * wv.y
                        + xv[i].z * wv.z + xv[i].w * wv.w;
                s += __shfl_xor_sync(0xFFFFFFFFu, s, 16);
                s += __shfl_xor_sync(0xFFFFFFFFu, s, 8);
                s += __shfl_xor_sync(0xFFFFFFFFu, s, 4);
                s += __shfl_xor_sync(0xFFFFFFFFu, s, 2);
                s += __shfl_xor_sync(0xFFFFFFFFu, s, 1);
                if (lane == 0)
                    cur_s[buf][(wid - 1) * T_PER_WARP + i] = s + bias_v;
            }
        }

        __syncthreads();   // chunk c dots visible

        // Scan thread consumes chunk c while dot warps loop around and start
        // fetching chunk c+1 into buf^1. 1-deep pipeline, safe (they can't
        // touch THIS buffer again until the next barrier).
        if (threadIdx.x == 0) {
            const int tbase = c * CHUNK;
            #pragma unroll 4
            for (int tl = 0; tl < CHUNK; ++tl) {
                float cu = cur_s[buf][tl];
                float u  = fmaf(BETA_F, v, cu);   // leaky integrate
                float um = u - 1.0f;              // off critical path
                bool  p  = (u >= 1.0f);           // threshold (VTH=1)
                v = p ? um : u;                   // subtraction reset
                ((float*)&spk4)[tl & 3] = p ? 1.0f : 0.0f;  // off critical path
                if ((tl & 3) == 3)
                    reinterpret_cast<float4*>(out_row + tbase + (tl - 3))[0] = spk4;
            }
        }
    }

    // final membrane potential vT
    if (threadIdx.x == 0 && out_size > B_SZ * T_SZ)
        out[B_SZ * T_SZ + b] = v;
}

extern "C" void kernel_launch(void* const* d_in, const int* in_sizes, int n_in,
                              void* d_out, int out_size)
{
    const float* x    = (const float*)d_in[0];  // [256, 2000, 128] fp32
    const float* W    = (const float*)d_in[1];  // [128, 1] fp32
    const float* bias = (const float*)d_in[2];  // [1] fp32
    float* out = (float*)d_out;                 // spikes [256*2000] then vT [256]

    lif_fused_kernel<<<B_SZ, THREADS>>>(x, W, bias, out, out_size);
}